// round 2
// baseline (speedup 1.0000x reference)
#include <cuda_runtime.h>
#include <cuda_bf16.h>

// ---------------- problem constants ----------------
constexpr int NU   = 4096;
constexpr int NS   = 8192;
constexpr int ND   = 32;
constexpr int NREG = 128;
#define GA_CONST 0.1

// ---------------- tiling ----------------
constexpr int TSB = 256;                  // items per block
constexpr int TUB = 64;                   // users per block
constexpr int SBLK = NS / TSB;            // 32 s-blocks per user row
constexpr int MAIN_BLOCKS = (NU / TUB) * SBLK;   // 2048
constexpr int REG_CTAS = 8;               // region-loss CTAs
constexpr int REG_PER_CTA = NREG / REG_CTAS;     // 16 regions each
constexpr int GRIDN = MAIN_BLOCKS + REG_CTAS;    // 2056

// ---------------- device scratch ----------------
__device__ double       g_acc  = 0.0;
__device__ unsigned int g_done = 0u;

// shared memory: main path and region path never coexist in one block
union SmemU {
    struct {
        unsigned item[TSB * 17];   // bf16x2 words, row stride 17 (conflict-light)
        unsigned user[TUB * 16];   // bf16x2 words, dense rows (uniform access)
        float    red[8];
    } m;                           // ~21.6 KB
    struct {
        int    idx[NU];            // 16 KB
        double dacc[8];
    } r;
};

static __device__ __forceinline__ __nv_bfloat162 asbf2(unsigned v) {
    return *reinterpret_cast<__nv_bfloat162*>(&v);
}

__global__ __launch_bounds__(256, 3)
void k_fused(const float* __restrict__ user_emb,
             const float* __restrict__ item_emb,
             const int*   __restrict__ mask,
             const float* __restrict__ tq,
             const float* __restrict__ wgt,
             const int*   __restrict__ ridx,
             float*       __restrict__ out)
{
    __shared__ SmemU sm;
    const int tid = threadIdx.x;
    const int b   = blockIdx.x;
    double blockpart = 0.0;   // meaningful on tid==0 only

    if (b < MAIN_BLOCKS) {
        // ================== main weighted-MSE tile ==================
        const int sbase = (b & (SBLK - 1)) * TSB;
        const int ubase = (b / SBLK) * TUB;

        // ---- stage item tile -> bf16 smem (row stride 17 words) ----
        {
            const float4* g = (const float4*)(item_emb + (size_t)sbase * ND);
#pragma unroll
            for (int i = 0; i < (TSB * ND) / (4 * 256); ++i) {   // 8 iters
                int idx = tid + i * 256;
                float4 v = g[idx];
                int f = idx * 4;
                int row = f >> 5;
                int col = (f & 31) >> 1;   // word column
                __nv_bfloat162 h0 = __floats2bfloat162_rn(v.x, v.y);
                __nv_bfloat162 h1 = __floats2bfloat162_rn(v.z, v.w);
                unsigned* p = &sm.m.item[row * 17 + col];
                p[0] = *reinterpret_cast<unsigned*>(&h0);
                p[1] = *reinterpret_cast<unsigned*>(&h1);
            }
        }
        // ---- stage user tile -> bf16 smem (dense rows, 16 words) ----
        {
            const float4* g = (const float4*)(user_emb + (size_t)ubase * ND);
#pragma unroll
            for (int i = 0; i < (TUB * ND) / (4 * 256); ++i) {   // 2 iters
                int idx = tid + i * 256;
                float4 v = g[idx];
                int f = idx * 4;
                int row = f >> 5;
                int col = (f & 31) >> 1;
                __nv_bfloat162 h0 = __floats2bfloat162_rn(v.x, v.y);
                __nv_bfloat162 h1 = __floats2bfloat162_rn(v.z, v.w);
                unsigned* p = &sm.m.user[row * 16 + col];
                p[0] = *reinterpret_cast<unsigned*>(&h0);
                p[1] = *reinterpret_cast<unsigned*>(&h1);
            }
        }
        __syncthreads();

        const int warp = tid >> 5, lane = tid & 31;
        const int strip = (warp & 3) * 64;       // 4 item strips of 64
        const int uhalf = (warp >> 2) * 32;      // 2 user halves of 32
        const int i0 = strip + 2 * lane;         // lane owns items i0, i0+1

        // item fragments: 2 rows x 16 bf16x2 (32 regs total)
        __nv_bfloat162 a0[16], a1[16];
        {
            const unsigned* r0 = &sm.m.item[i0 * 17];
            const unsigned* r1 = r0 + 17;
#pragma unroll
            for (int k = 0; k < 16; ++k) { a0[k] = asbf2(r0[k]); a1[k] = asbf2(r1[k]); }
        }

        const long base = (long)(ubase + uhalf) * NS + sbase + i0;
        const uint4* uvbase = (const uint4*)&sm.m.user[uhalf * 16];

        float lsum = 0.0f;
#pragma unroll 4
        for (int u = 0; u < 32; ++u) {
            const long off = base + (long)u * NS;
            const int2   m2 = __ldcs((const int2*)  (mask + off));
            const float2 t2 = __ldcs((const float2*)(tq   + off));
            const float2 w2 = __ldcs((const float2*)(wgt  + off));

            // user row: 4 uniform LDS.128 -> 16 bf16x2
            uint4 q0 = uvbase[u * 4 + 0];
            uint4 q1 = uvbase[u * 4 + 1];
            uint4 q2 = uvbase[u * 4 + 2];
            uint4 q3 = uvbase[u * 4 + 3];
            unsigned uw[16] = {q0.x,q0.y,q0.z,q0.w, q1.x,q1.y,q1.z,q1.w,
                               q2.x,q2.y,q2.z,q2.w, q3.x,q3.y,q3.z,q3.w};

            __nv_bfloat162 z = __floats2bfloat162_rn(0.f, 0.f);
            __nv_bfloat162 c0a = z, c0b = z, c1a = z, c1b = z;  // 2 chains/item
#pragma unroll
            for (int k = 0; k < 16; k += 2) {
                __nv_bfloat162 ua = asbf2(uw[k]);
                __nv_bfloat162 ub = asbf2(uw[k + 1]);
                c0a = __hfma2(a0[k],     ua, c0a);
                c0b = __hfma2(a0[k + 1], ub, c0b);
                c1a = __hfma2(a1[k],     ua, c1a);
                c1b = __hfma2(a1[k + 1], ub, c1b);
            }
            __nv_bfloat162 s0 = __hadd2(c0a, c0b);
            __nv_bfloat162 s1 = __hadd2(c1a, c1b);
            float dot0 = __low2float(s0) + __high2float(s0);
            float dot1 = __low2float(s1) + __high2float(s1);
            float p0 = m2.x ? dot0 : 0.0f;
            float p1 = m2.y ? dot1 : 0.0f;
            float d0 = p0 - t2.x;
            float d1 = p1 - t2.y;
            lsum = fmaf(w2.x * d0, d0, lsum);
            lsum = fmaf(w2.y * d1, d1, lsum);
        }

        // reduce block -> blockpart
#pragma unroll
        for (int o = 16; o; o >>= 1) lsum += __shfl_xor_sync(0xffffffffu, lsum, o);
        if (lane == 0) sm.m.red[warp] = lsum;
        __syncthreads();
        if (tid == 0) {
            float s = 0.0f;
#pragma unroll
            for (int i = 0; i < 8; ++i) s += sm.m.red[i];
            blockpart = (double)s;
        }
    } else {
        // ================== region LOO-deviation loss ==================
        const int rbase = (b - MAIN_BLOCKS) * REG_PER_CTA;
        for (int i = tid; i < NU; i += 256) sm.r.idx[i] = ridx[i];
        __syncthreads();

        const int warp = tid >> 5, lane = tid & 31;
        double wacc = 0.0;
#pragma unroll 1
        for (int rr = 0; rr < 2; ++rr) {
            const int r = rbase + warp * 2 + rr;
            float sum_d = 0.0f;   // per-lane = per-dim region sum
            int   cnt   = 0;
            for (int c = 0; c < NU / 32; ++c) {
                int ui = sm.r.idx[c * 32 + lane];
                unsigned mb = __ballot_sync(0xffffffffu, ui == r);
                cnt += __popc(mb);
                while (mb) {
                    int bit = __ffs(mb) - 1; mb &= mb - 1;
                    int u = c * 32 + bit;
                    sum_d += user_emb[(size_t)u * ND + lane];   // coalesced row
                }
            }
            if (cnt > 1) {
                float inv = 1.0f / ((float)cnt - 1.0f);
                float dsum = 0.0f;
                for (int c = 0; c < NU / 32; ++c) {
                    int ui = sm.r.idx[c * 32 + lane];
                    unsigned mb = __ballot_sync(0xffffffffu, ui == r);
                    while (mb) {
                        int bit = __ffs(mb) - 1; mb &= mb - 1;
                        int u = c * 32 + bit;
                        float e = user_emb[(size_t)u * ND + lane];
                        float loo = (sum_d - e) * inv;
                        dsum += fabsf(e - loo);
                    }
                }
#pragma unroll
                for (int o = 16; o; o >>= 1) dsum += __shfl_xor_sync(0xffffffffu, dsum, o);
                if (lane == 0) wacc += (double)dsum;
            }
        }
        if (lane == 0) sm.r.dacc[warp] = wacc;
        __syncthreads();
        if (tid == 0) {
            double t = 0.0;
#pragma unroll
            for (int i = 0; i < 8; ++i) t += sm.r.dacc[i];
            blockpart = GA_CONST * t;
        }
    }

    // ================== common epilogue: accumulate, last block writes ==================
    if (tid == 0) {
        atomicAdd(&g_acc, blockpart);
        __threadfence();
        unsigned old = atomicAdd(&g_done, 1u);
        if (old == (unsigned)(GRIDN - 1)) {
            __threadfence();
            out[0] = (float)g_acc;
            g_acc  = 0.0;     // reset for next graph replay
            g_done = 0u;
        }
    }
}

// ---------------- launch ----------------
extern "C" void kernel_launch(void* const* d_in, const int* in_sizes, int n_in,
                              void* d_out, int out_size) {
    const float* user_emb = (const float*)d_in[0];
    const float* item_emb = (const float*)d_in[1];
    const int*   mask     = (const int*)  d_in[2];
    const float* tq       = (const float*)d_in[3];
    const float* wgt      = (const float*)d_in[4];
    const int*   ridx     = (const int*)  d_in[5];

    k_fused<<<GRIDN, 256>>>(user_emb, item_emb, mask, tq, wgt, ridx, (float*)d_out);
}

// round 4
// speedup vs baseline: 1.4153x; 1.4153x over previous
#include <cuda_runtime.h>
#include <cuda_bf16.h>
#include <cstdint>

// ---------------- problem constants ----------------
constexpr int NU   = 4096;
constexpr int NS   = 8192;
constexpr int ND   = 32;
constexpr int NREG = 128;
#define GA_CONST 0.1

// ---------------- tiling ----------------
constexpr int TSB = 256;                 // items per block (8 warps x 32 items)
constexpr int TUB = 64;                  // users per block
constexpr int SBLK = NS / TSB;           // 32
constexpr int UBLK = NU / TUB;           // 64
constexpr int MAIN = SBLK * UBLK;        // 2048
constexpr int REGB = 128;                // region-loss blocks (32 users each)
constexpr int GRIDN = MAIN + REGB;       // 2176

// k_pre sizing
constexpr int CONV_F4 = (NU * ND + NS * ND) / 4;   // 98304 float4s
constexpr int CONV_BLOCKS = CONV_F4 / 256;         // 384
constexpr int RSUM_BLOCKS = NU / 256;              // 16
constexpr int PRE_GRID = CONV_BLOCKS + RSUM_BLOCKS;

// ---------------- device scratch (zero-init at load; reset each replay) ----------------
__device__ double       g_acc  = 0.0;
__device__ unsigned int g_done = 0u;
__device__ float        g_rsum[NREG * ND];          // zero-init
__device__ float        g_rcnt[NREG];               // zero-init
__device__ unsigned     g_ue[NU * ND / 2];          // user emb bf16x2 words
__device__ unsigned     g_ie[NS * ND / 2];          // item emb bf16x2 words

static __device__ __forceinline__ __nv_bfloat162 asbf2(unsigned v) {
    return *reinterpret_cast<__nv_bfloat162*>(&v);
}

// ---------------- kernel 1: bf16 convert + region segment sums ----------------
__global__ void k_pre(const float* __restrict__ user_emb,
                      const float* __restrict__ item_emb,
                      const int*   __restrict__ ridx) {
    const int b = blockIdx.x, t = threadIdx.x;
    if (b < CONV_BLOCKS) {
        int idx = b * 256 + t;                       // float4 id
        constexpr int UF4 = NU * ND / 4;             // 32768
        float4 f;
        unsigned* dst;
        if (idx < UF4) {
            f = ((const float4*)user_emb)[idx];
            dst = &g_ue[idx * 2];
        } else {
            int v = idx - UF4;
            f = ((const float4*)item_emb)[v];
            dst = &g_ie[v * 2];
        }
        __nv_bfloat162 h0 = __floats2bfloat162_rn(f.x, f.y);
        __nv_bfloat162 h1 = __floats2bfloat162_rn(f.z, f.w);
        dst[0] = *reinterpret_cast<unsigned*>(&h0);
        dst[1] = *reinterpret_cast<unsigned*>(&h1);
    } else {
        // region segment sums: warp handles 32 users, lane = dim
        const int rb = b - CONV_BLOCKS;
        const int warp = t >> 5, lane = t & 31;
        const int u0 = rb * 256 + warp * 32;
#pragma unroll 4
        for (int k = 0; k < 32; ++k) {
            int u = u0 + k;
            int r = __ldg(ridx + u);
            float e = user_emb[(size_t)u * ND + lane];
            atomicAdd(&g_rsum[r * ND + lane], e);
            if (lane == 0) atomicAdd(&g_rcnt[r], 1.0f);
        }
    }
}

// ---------------- kernel 2: fused loss ----------------
__global__ __launch_bounds__(256, 3)
void k_main(const float* __restrict__ user_emb,
            const int*   __restrict__ mask,
            const float* __restrict__ tq,
            const float* __restrict__ wgt,
            const int*   __restrict__ ridx,
            float*       __restrict__ out)
{
    __shared__ unsigned s_item[TSB * 17];   // item words, row stride 17 (conflict-free)
    __shared__ unsigned s_user[TUB * 16];   // user words, dense rows
    __shared__ float    s_red[8];
    __shared__ double   s_dacc[8];
    __shared__ int      s_last;

    const int tid  = threadIdx.x;
    const int b    = blockIdx.x;
    const int warp = tid >> 5, lane = tid & 31;
    double blockpart = 0.0;

    if (b < MAIN) {
        // ============ main tile: 256 items x 64 users ============
        const int sbase = (b & (SBLK - 1)) * TSB;
        const int ubase = (b >> 5) * TUB;           // b / SBLK

        // stage item tile (4096 words) and user tile (1024 words)
        {
            const unsigned* gi = g_ie + (size_t)sbase * (ND / 2);
#pragma unroll
            for (int i = 0; i < 16; ++i) {
                int w = tid + i * 256;
                s_item[(w >> 4) * 17 + (w & 15)] = gi[w];
            }
            const unsigned* gu = g_ue + (size_t)ubase * (ND / 2);
#pragma unroll
            for (int i = 0; i < 4; ++i) {
                int w = tid + i * 256;
                s_user[w] = gu[w];
            }
        }
        __syncthreads();

        // item fragment: this lane's item row (16 bf16x2 words)
        const int irow = warp * 32 + lane;          // local item 0..255
        __nv_bfloat162 a[16];
        {
            const unsigned* p = &s_item[irow * 17];
#pragma unroll
            for (int k = 0; k < 16; ++k) a[k] = asbf2(p[k]);
        }

        const int srow = sbase + irow;
        const size_t base = (size_t)ubase * NS + srow;
        const __nv_bfloat162 zero2 = __floats2bfloat162_rn(0.f, 0.f);

        float lsum = 0.0f;
#pragma unroll 2
        for (int ub = 0; ub < TUB; ub += 4) {
            // ---- batch loads: 12 independent LDGs in flight ----
            int   mm[4];
            float tt[4], ww[4];
#pragma unroll
            for (int j = 0; j < 4; ++j) {
                const size_t off = base + (size_t)(ub + j) * NS;
                mm[j] = __ldcs(mask + off);
                tt[j] = __ldcs(tq   + off);
                ww[j] = __ldcs(wgt  + off);
            }
            // ---- compute 4 dots ----
#pragma unroll
            for (int j = 0; j < 4; ++j) {
                const uint4* q = (const uint4*)&s_user[(ub + j) * 16];
                uint4 q0 = q[0], q1 = q[1], q2 = q[2], q3 = q[3];
                unsigned uw[16] = {q0.x,q0.y,q0.z,q0.w, q1.x,q1.y,q1.z,q1.w,
                                   q2.x,q2.y,q2.z,q2.w, q3.x,q3.y,q3.z,q3.w};
                __nv_bfloat162 ca = zero2, cb = zero2;
#pragma unroll
                for (int k = 0; k < 16; k += 2) {
                    ca = __hfma2(a[k],     asbf2(uw[k]),     ca);
                    cb = __hfma2(a[k + 1], asbf2(uw[k + 1]), cb);
                }
                __nv_bfloat162 s2 = __hadd2(ca, cb);
                float dot = __low2float(s2) + __high2float(s2);
                float p = mm[j] ? dot : 0.0f;
                float d = p - tt[j];
                lsum = fmaf(ww[j] * d, d, lsum);
            }
        }

        // block reduce
#pragma unroll
        for (int o = 16; o; o >>= 1) lsum += __shfl_xor_sync(0xffffffffu, lsum, o);
        if (lane == 0) s_red[warp] = lsum;
        __syncthreads();
        if (tid == 0) {
            float s = 0.0f;
#pragma unroll
            for (int i = 0; i < 8; ++i) s += s_red[i];
            blockpart = (double)s;
        }
    } else {
        // ============ region LOO-deviation: warp = 4 users, lane = dim ============
        const int rb = b - MAIN;                    // 0..127
        const int u0 = rb * 32 + warp * 4;
        double wacc = 0.0;
#pragma unroll
        for (int k = 0; k < 4; ++k) {
            int u = u0 + k;
            int r = ridx[u];
            float cnt = g_rcnt[r];
            float e   = user_emb[(size_t)u * ND + lane];
            float loo = (g_rsum[r * ND + lane] - e) / fmaxf(cnt - 1.0f, 1.0f);
            float dev = fabsf(e - loo);
#pragma unroll
            for (int o = 16; o; o >>= 1) dev += __shfl_xor_sync(0xffffffffu, dev, o);
            if (lane == 0 && cnt > 1.0f) wacc += (double)dev;
        }
        if (lane == 0) s_dacc[warp] = wacc;
        __syncthreads();
        if (tid == 0) {
            double t = 0.0;
#pragma unroll
            for (int i = 0; i < 8; ++i) t += s_dacc[i];
            blockpart = GA_CONST * t;
        }
    }

    // ============ epilogue: accumulate; last block writes + resets scratch ============
    if (tid == 0) {
        atomicAdd(&g_acc, blockpart);
        __threadfence();
        unsigned old = atomicAdd(&g_done, 1u);
        s_last = (old == (unsigned)(GRIDN - 1));
    }
    __syncthreads();
    if (s_last) {
        // whole block resets region scratch for the next graph replay
        for (int i = tid; i < NREG * ND; i += 256) g_rsum[i] = 0.0f;
        if (tid < NREG) g_rcnt[tid] = 0.0f;
        __syncthreads();
        if (tid == 0) {
            __threadfence();
            out[0] = (float)g_acc;
            g_acc  = 0.0;
            g_done = 0u;
        }
    }
}

// ---------------- launch ----------------
extern "C" void kernel_launch(void* const* d_in, const int* in_sizes, int n_in,
                              void* d_out, int out_size) {
    const float* user_emb = (const float*)d_in[0];
    const float* item_emb = (const float*)d_in[1];
    const int*   mask     = (const int*)  d_in[2];
    const float* tq       = (const float*)d_in[3];
    const float* wgt      = (const float*)d_in[4];
    const int*   ridx     = (const int*)  d_in[5];

    k_pre<<<PRE_GRID, 256>>>(user_emb, item_emb, ridx);
    k_main<<<GRIDN, 256>>>(user_emb, mask, tq, wgt, ridx, (float*)d_out);
}